// round 15
// baseline (speedup 1.0000x reference)
#include <cuda_runtime.h>
#include <cuda_bf16.h>
#include <math.h>

#define NB 32

// ---------------- device globals ----------------
__device__ float2 gA[NB * 16 * 128 * 64];  // [b][ky][m][i]
__device__ float2 gY[NB * 32 * 16 * 64];
__device__ float2 gT[NB * 32 * 16 * 64];
__device__ float2 gD[NB * 128 * 16 * 64];
// transposed spectral weights
__device__ float2 gW0t[65536], gW1t[65536], gW2t[65536], gW3t[65536];
// duplicated inverse-ky basis: E2[v*32+c] = {e,e}
__device__ __align__(16) float2 gE2[4096];
// packed twiddles: k1 [kg][n][4] {cos,-sin}; k2 [ug][m][4] {cos,sin}
__device__ __align__(16) float2 gTwK1p[4096];
__device__ __align__(16) float2 gTw2p[2048];
// pre-built mma B-fragments
__device__ __align__(16) unsigned gF1[16384];
__device__ __align__(16) unsigned gF2[16384];

// ---------------- helpers ----------------
typedef unsigned long long ull;
__device__ __forceinline__ ull pack2(float lo, float hi) {
    ull r;
    asm("mov.b64 %0, {%1,%2};" : "=l"(r) : "f"(lo), "f"(hi));
    return r;
}
__device__ __forceinline__ void unpack2(ull v, float& lo, float& hi) {
    asm("mov.b64 {%0,%1}, %2;" : "=f"(lo), "=f"(hi) : "l"(v));
}
__device__ __forceinline__ void ffma2(ull& d, ull a, ull b) {
    asm("fma.rn.f32x2 %0, %1, %2, %0;" : "+l"(d) : "l"(a), "l"(b));
}
__device__ __forceinline__ unsigned smem_u32(const void* p) {
    unsigned a;
    asm("{ .reg .u64 t; cvta.to.shared.u64 t, %1; cvt.u32.u64 %0, t; }" : "=r"(a) : "l"(p));
    return a;
}
__device__ __forceinline__ void ldm4(unsigned* r, unsigned addr) {
    asm volatile("ldmatrix.sync.aligned.m8n8.x4.shared.b16 {%0,%1,%2,%3}, [%4];"
                 : "=r"(r[0]), "=r"(r[1]), "=r"(r[2]), "=r"(r[3]) : "r"(addr));
}
__device__ __forceinline__ void mma16816(float* c, const unsigned* a, const unsigned* b) {
    asm volatile("mma.sync.aligned.m16n8k16.row.col.f32.bf16.bf16.f32 "
                 "{%0,%1,%2,%3}, {%4,%5,%6,%7}, {%8,%9}, {%0,%1,%2,%3};"
                 : "+f"(c[0]), "+f"(c[1]), "+f"(c[2]), "+f"(c[3])
                 : "r"(a[0]), "r"(a[1]), "r"(a[2]), "r"(a[3]), "r"(b[0]), "r"(b[1]));
}
__device__ __forceinline__ void split2(float v0, float v1, unsigned& hp, unsigned& lp) {
    asm("cvt.rn.bf16x2.f32 %0, %1, %2;" : "=r"(hp) : "f"(v1), "f"(v0));
    float h0 = __uint_as_float(hp << 16);
    float h1 = __uint_as_float(hp & 0xFFFF0000u);
    float l0 = v0 - h0, l1 = v1 - h1;
    asm("cvt.rn.bf16x2.f32 %0, %1, %2;" : "=r"(lp) : "f"(l1), "f"(l0));
}

// ---------------- prep: B-fragments via real ldmatrix ----------------
__global__ void prep_frag(const float* __restrict__ bw1, const float* __restrict__ fw1,
                          const float* __restrict__ bw2, const float* __restrict__ fw2) {
    extern __shared__ __align__(16) char ps[];
    int p = blockIdx.x, t = threadIdx.x, w = t >> 5, l = t & 31;
    const float* W1 = p ? fw1 : bw1;
    const float* W2 = p ? fw2 : bw2;
    for (int e = t; e < 9216; e += 256) {
        int n = e / 72, k = e % 72;
        float v = (k < 64) ? W1[k * 128 + n] : 0.f;
        __nv_bfloat16 hi = __float2bfloat16(v);
        __nv_bfloat16 lo = __float2bfloat16(v - __bfloat162float(hi));
        ((unsigned short*)(ps + 0))[e] = __bfloat16_as_ushort(hi);
        ((unsigned short*)(ps + 18432))[e] = __bfloat16_as_ushort(lo);
    }
    for (int e = t; e < 8704; e += 256) {
        int n = e / 136, k = e % 136;
        float v = (k < 128) ? W2[k * 64 + n] : 0.f;
        __nv_bfloat16 hi = __float2bfloat16(v);
        __nv_bfloat16 lo = __float2bfloat16(v - __bfloat162float(hi));
        ((unsigned short*)(ps + 36864))[e] = __bfloat16_as_ushort(hi);
        ((unsigned short*)(ps + 54272))[e] = __bfloat16_as_ushort(lo);
    }
    __syncthreads();
    unsigned sb = smem_u32(ps);
    unsigned kB = ((l >> 3) & 1) * 8;
    if (w < 4) {
        int wn = w;
        unsigned rowB = (unsigned)(wn * 32 + ((l >> 4) << 3) + (l & 7));
        for (int ki = 0; ki < 4; ki++)
            for (int term = 0; term < 2; term++)
                for (int h2 = 0; h2 < 2; h2++) {
                    unsigned r[4];
                    ldm4(r, sb + (term ? 18432u : 0u) + rowB * 144 + kB * 2 +
                            (unsigned)ki * 32 + (unsigned)h2 * (16 * 144));
                    ((uint4*)gF1)[((((p * 4 + wn) * 4 + ki) * 2 + term) * 2 + h2) * 32 + l] =
                        make_uint4(r[0], r[1], r[2], r[3]);
                }
    } else {
        int wn = w - 4;
        unsigned rowB = (unsigned)(wn * 16 + ((l >> 4) << 3) + (l & 7));
        for (int ki = 0; ki < 8; ki++)
            for (int term = 0; term < 2; term++) {
                unsigned r[4];
                ldm4(r, sb + (term ? 54272u : 36864u) + rowB * 272 + kB * 2 + (unsigned)ki * 32);
                ((uint4*)gF2)[(((p * 4 + wn) * 8 + ki) * 2 + term) * 32 + l] =
                    make_uint4(r[0], r[1], r[2], r[3]);
            }
    }
}

// ---------------- prep: transpose spectral weights (tiled, coalesced) ----------------
// grid: 256 blocks = 4 weights * 64 tiles of 64 ij-rows. block 256 thr.
__global__ void prep_spec(const float* __restrict__ w0, const float* __restrict__ w1,
                          const float* __restrict__ w2, const float* __restrict__ w3) {
    __shared__ float2 tile[64][17];  // [ij][lx], padded
    int wsel = blockIdx.x >> 6, tb = blockIdx.x & 63;
    const float2* src;
    float2* dst;
    switch (wsel) {
        case 0: src = (const float2*)w0; dst = gW0t; break;
        case 1: src = (const float2*)w1; dst = gW1t; break;
        case 2: src = (const float2*)w2; dst = gW2t; break;
        default: src = (const float2*)w3; dst = gW3t; break;
    }
    int t = threadIdx.x;
    // load 64 ij rows x 16 lx, coalesced along lx
    for (int e = t; e < 1024; e += 256) {
        int ij = e >> 4, lx = e & 15;
        tile[ij][lx] = src[(tb * 64 + ij) * 16 + lx];
    }
    __syncthreads();
    // store transposed: dst[lx*4096 + ij_global], coalesced along ij
    for (int e = t; e < 1024; e += 256) {
        int lx = e >> 6, ij = e & 63;
        dst[lx * 4096 + tb * 64 + ij] = tile[ij][lx];
    }
}

// ---------------- prep: E table + packed twiddles ----------------
__global__ void prep_e() {
    int e = blockIdx.x * 256 + threadIdx.x;
    if (e < 4096) {
        int v = e >> 5, c = e & 31, k = c >> 1;
        float sv, cv;
        sincospif((float)(v * k) * (1.0f / 64.0f), &sv, &cv);
        float val = (c & 1) ? sv : cv;
        gE2[e] = make_float2(val, val);
    } else if (e < 8192) {
        int e2 = e - 4096;
        int kg = e2 >> 8, n = (e2 >> 2) & 63, j = e2 & 3;
        int ky = kg * 4 + j;
        float sv, cv;
        sincospif((float)(ky * n) * (1.0f / 64.0f), &sv, &cv);
        gTwK1p[e2] = make_float2(cv, -sv);
    } else if (e < 10240) {
        int e2 = e - 8192;
        int ug = e2 >> 9, m = (e2 >> 2) & 127, q = e2 & 3;
        int k = ug * 4 + q + 1;
        float sv, cv;
        sincospif((float)(k * m) * (1.0f / 64.0f), &sv, &cv);
        gTw2p[e2] = make_float2(cv, sv);
    }
}

// ---------------- K1: forward DFT along n (fold-on-load) ----------------
__global__ __launch_bounds__(256) void k1_stageA(const float* __restrict__ x) {
    extern __shared__ float smf[];
    float2* sd = (float2*)smf;
    float2* twk = (float2*)(smf + 8064);
    float* r064 = smf + 8064 + 2048;
    int bm = blockIdx.x, t = threadIdx.x;
    const float* xf = x + (size_t)bm * 8192;
    const float4* xg = (const float4*)xf;

    if (t < 64) r064[t] = xf[t];
    else if (t < 128) r064[t] = xf[4096 + (t - 64)];
    #pragma unroll
    for (int e = t; e < 512; e += 256) ((float4*)twk)[e] = ((const float4*)gTwK1p)[e];
    for (int e = t; e < 1008; e += 256) {
        int n = 1 + (e >> 4), i4 = e & 15;
        float4 a = xg[n * 16 + i4];
        float4 b = xg[(128 - n) * 16 + i4];
        float4* dst = (float4*)&sd[(n - 1) * 64 + i4 * 4];
        dst[0] = make_float4(a.x + b.x, a.x - b.x, a.y + b.y, a.y - b.y);
        dst[1] = make_float4(a.z + b.z, a.z - b.z, a.w + b.w, a.w - b.w);
    }
    __syncthreads();

    int i = t & 63, kg = t >> 6;
    int ky0 = kg * 4;
    float x0 = r064[i], x64 = r064[64 + i];
    const ull* sd2 = (const ull*)sd + i;
    const ulonglong2* twp = (const ulonglong2*)twk + kg * 128;
    ull a0 = pack2(x0 + x64, 0.f);
    ull a1 = pack2(x0 - x64, 0.f);
    ull a2 = pack2(x0 + x64, 0.f);
    ull a3 = pack2(x0 - x64, 0.f);
    #pragma unroll
    for (int n = 1; n <= 63; n++) {
        ull sdv = sd2[(n - 1) * 64];
        ulonglong2 t01 = twp[n * 2];
        ulonglong2 t23 = twp[n * 2 + 1];
        ffma2(a0, sdv, t01.x);
        ffma2(a1, sdv, t01.y);
        ffma2(a2, sdv, t23.x);
        ffma2(a3, sdv, t23.y);
    }
    int b = bm >> 7, m = bm & 127;
    float2* outp = gA + ((size_t)b * 16) * 8192 + (size_t)m * 64 + i;
    float lo, hi;
    unpack2(a0, lo, hi); outp[(size_t)(ky0 + 0) * 8192] = make_float2(lo, hi);
    unpack2(a1, lo, hi); outp[(size_t)(ky0 + 1) * 8192] = make_float2(lo, hi);
    unpack2(a2, lo, hi); outp[(size_t)(ky0 + 2) * 8192] = make_float2(lo, hi);
    unpack2(a3, lo, hi); outp[(size_t)(ky0 + 3) * 8192] = make_float2(lo, hi);
}

// ---------------- K2: forward DFT along m (two half-passes, 48KB smem) ----------------
__global__ __launch_bounds__(256) void k2_stageB() {
    extern __shared__ float2 sm2[];
    float2* As = sm2;
    float2* tw = sm2 + 4096;
    int blk = blockIdx.x, b = blk >> 4, ky = blk & 15, t = threadIdx.x;
    #pragma unroll
    for (int e = t; e < 1024; e += 256) ((float4*)tw)[e] = ((const float4*)gTw2p)[e];

    int i = t & 63, ug = t >> 6;
    ull acc12[4], acc34[4];
    #pragma unroll
    for (int q = 0; q < 4; q++) { acc12[q] = 0ull; acc34[q] = 0ull; }
    const ulonglong2* twp = (const ulonglong2*)tw + ug * 256;
    float sx = 0.f, sy = 0.f;

    const float4* src = (const float4*)(gA + (size_t)blk * 8192);
    #pragma unroll
    for (int ph = 0; ph < 2; ph++) {
        __syncthreads();
        #pragma unroll
        for (int e = t; e < 2048; e += 256) ((float4*)As)[e] = src[ph * 2048 + e];
        __syncthreads();
        #pragma unroll 4
        for (int mm = 0; mm < 64; mm++) {
            int m = ph * 64 + mm;
            float2 a = As[mm * 64 + i];
            ull axy = pack2(a.x, a.y), ayx = pack2(a.y, a.x);
            ulonglong2 t01 = twp[m * 2];
            ulonglong2 t23 = twp[m * 2 + 1];
            ffma2(acc12[0], axy, t01.x); ffma2(acc34[0], ayx, t01.x);
            ffma2(acc12[1], axy, t01.y); ffma2(acc34[1], ayx, t01.y);
            ffma2(acc12[2], axy, t23.x); ffma2(acc34[2], ayx, t23.x);
            ffma2(acc12[3], axy, t23.y); ffma2(acc34[3], ayx, t23.y);
            if (ug == 3) { sx += a.x; sy += a.y; }
        }
    }
    float2* yb = gY + (((size_t)b * 32) * 16 + ky) * 64 + i;
    #pragma unroll
    for (int q = 0; q < 4; q++) {
        int k = ug * 4 + q + 1;
        float u1, u2, u3, u4;
        unpack2(acc12[q], u1, u2);
        unpack2(acc34[q], u3, u4);
        if (k < 16) yb[(size_t)k * 1024] = make_float2(u1 + u2, u3 - u4);
        yb[(size_t)(32 - k) * 1024] = make_float2(u1 - u2, u3 + u4);
    }
    if (ug == 3) yb[0] = make_float2(sx, sy);
}

// ---------------- K3a ----------------
__global__ __launch_bounds__(256) void k3a_mix1() {
    __shared__ float4 Ys4[16 * 64];
    __shared__ float2 Was[64 * 64];
    int blk = blockIdx.x, s = blk & 31, lx = s & 15, t = threadIdx.x;
    const float2* wt = (s < 16) ? gW0t : gW2t;
    for (int e = t; e < 1024; e += 256) {
        float2 y = gY[(size_t)blk * 1024 + e];
        Ys4[e] = make_float4(y.x, y.y, -y.y, y.x);
    }
    for (int e = t; e < 4096; e += 256) Was[e] = wt[lx * 4096 + e];
    __syncthreads();
    int j = t & 63, kg = t >> 6;
    ull acc[4];
    #pragma unroll
    for (int q = 0; q < 4; q++) acc[q] = 0ull;
    for (int ii = 0; ii < 64; ii++) {
        float2 wv = Was[ii * 64 + j];
        ull wr2 = pack2(wv.x, wv.x), wi2 = pack2(wv.y, wv.y);
        #pragma unroll
        for (int q = 0; q < 4; q++) {
            const ull* y2 = (const ull*)&Ys4[(kg * 4 + q) * 64 + ii];
            ffma2(acc[q], wr2, y2[0]);
            ffma2(acc[q], wi2, y2[1]);
        }
    }
    #pragma unroll
    for (int q = 0; q < 4; q++) {
        float re, im;
        unpack2(acc[q], re, im);
        gT[(size_t)blk * 1024 + (kg * 4 + q) * 64 + j] = make_float2(re, im);
    }
}

// ---------------- K3b4 (fused): second channel mix + inverse DFT over kx ----------------
__global__ __launch_bounds__(256) void k3b4_mix_inv() {
    extern __shared__ __align__(16) char smb[];
    float4* Ts4 = (float4*)smb;
    float2* Wb0 = (float2*)(smb + 32768);
    float2* Wb1 = (float2*)(smb + 65536);
    float4* tab4 = (float4*)(smb + 98304);
    float2* Fs = (float2*)(smb + 32768);
    float4* PQ = (float4*)(smb + 49152);
    int blk = blockIdx.x, b = blk >> 4, ky = blk & 15, t = threadIdx.x;

    for (int e = t; e < 2048; e += 256) {
        int s_ = e >> 6, j = e & 63;
        float2 tv = gT[(((size_t)b * 32 + s_) * 16 + ky) * 64 + j];
        Ts4[e] = make_float4(tv.x, tv.y, -tv.y, tv.x);
    }
    for (int e = t; e < 4096; e += 256) {
        Wb0[e] = gW1t[ky * 4096 + e];
        Wb1[e] = gW3t[ky * 4096 + e];
    }
    if (t < 128) {
        float sv, cv;
        sincospif((float)t * (1.0f / 64.0f), &sv, &cv);
        tab4[t] = make_float4(cv, cv, sv, sv);
    }
    __syncthreads();

    int o = t & 63, sg = t >> 6;
    const float2* Wb = (sg < 2) ? Wb0 : Wb1;
    ull acc[8];
    #pragma unroll
    for (int q = 0; q < 8; q++) acc[q] = 0ull;
    for (int j = 0; j < 64; j++) {
        float2 wv = Wb[j * 64 + o];
        ull wr2 = pack2(wv.x, wv.x), wi2 = pack2(wv.y, wv.y);
        #pragma unroll
        for (int q = 0; q < 8; q++) {
            ulonglong2 tp = *(const ulonglong2*)&Ts4[(sg * 8 + q) * 64 + j];
            ffma2(acc[q], wr2, tp.x);
            ffma2(acc[q], wi2, tp.y);
        }
    }
    __syncthreads();
    #pragma unroll
    for (int q = 0; q < 8; q++) {
        int s_ = sg * 8 + q;
        float re, im;
        unpack2(acc[q], re, im);
        Fs[s_ * 64 + o] = make_float2(re, im);
    }
    __syncthreads();

    for (int e = t; e < 1024; e += 256) {
        int k = e >> 6, oo = e & 63;
        if (k == 0) {
            float2 f = Fs[16 * 64 + oo];
            PQ[oo] = make_float4(f.x, f.y, f.y, -f.x);
        } else {
            float2 fa = Fs[k * 64 + oo], fb = Fs[(32 - k) * 64 + oo];
            PQ[k * 64 + oo] = make_float4(fa.x + fb.x, fa.y + fb.y, -(fa.y - fb.y), fa.x - fb.x);
        }
    }
    __syncthreads();

    int ug = t >> 6;
    float2 F0 = Fs[o];
    float4 pq[16];
    #pragma unroll
    for (int k = 0; k < 16; k++) pq[k] = PQ[k * 64 + o];

    for (int q = 0; q < 32; q++) {
        int u = ug * 32 + q;
        ull acc2 = pack2(F0.x, F0.y);
        int idx = u;
        #pragma unroll
        for (int k = 1; k < 16; k++) {
            const ull* cs = (const ull*)&tab4[idx];
            ffma2(acc2, cs[0], ((const ull*)&pq[k])[0]);
            ffma2(acc2, cs[1], ((const ull*)&pq[k])[1]);
            idx = (idx + u) & 127;
        }
        {
            const ull* cs = (const ull*)&tab4[(16 * u) & 127];
            ffma2(acc2, cs[0], ((const ull*)&pq[0])[0]);
            ffma2(acc2, cs[1], ((const ull*)&pq[0])[1]);
        }
        float re, im;
        unpack2(acc2, re, im);
        gD[(((size_t)b * 128 + u) * 16 + ky) * 64 + o] = make_float2(re, im);
    }
}

// ---------------- K5: inverse ky + both MLPs (W frags + E from global) ----------------
#define OFF_XHI   0u
#define OFF_XLO   18432u
#define OFF_HHI   36864u
#define OFF_HLO   71680u
#define SMEM_K5   106496

__global__ __launch_bounds__(256, 2) void k5_mma(
    const float* __restrict__ bb1, const float* __restrict__ bb2,
    const float* __restrict__ fb1, const float* __restrict__ fb2,
    float* __restrict__ out) {
    extern __shared__ __align__(16) char sm[];
    unsigned sb = smem_u32(sm);
    int t = threadIdx.x, w = t >> 5, l = t & 31;
    int blk = blockIdx.x;

    // Dp staged in scratch (aliases H region); E read directly from gE2 (L1-resident)
    float* Dp = (float*)(sm + OFF_HHI);
    for (int e = t; e < 1024; e += 256) {
        int ky = e >> 6, o = e & 63;
        float2 d = gD[(size_t)blk * 1024 + e];
        float sc = (ky ? 2.0f : 1.0f) * (1.0f / 16384.0f);
        Dp[(2 * ky) * 64 + o] = d.x * sc;
        Dp[(2 * ky + 1) * 64 + o] = -d.y * sc;
    }
    __syncthreads();

    {
        int rg = t >> 4, cg = t & 15;
        int r0 = rg * 8, c0 = cg * 4;
        ull acc[8][2];
        #pragma unroll
        for (int j = 0; j < 8; j++) { acc[j][0] = 0ull; acc[j][1] = 0ull; }
        const ull* E2u = (const ull*)gE2;
        for (int c = 0; c < 32; c++) {
            ulonglong2 dd = *(const ulonglong2*)&Dp[c * 64 + c0];
            #pragma unroll
            for (int j = 0; j < 8; j++) {
                ull e2 = __ldg(&E2u[(r0 + j) * 32 + c]);
                ffma2(acc[j][0], e2, dd.x);
                ffma2(acc[j][1], e2, dd.y);
            }
        }
        #pragma unroll
        for (int j = 0; j < 8; j++) {
            float x0, x1, x2, x3;
            unpack2(acc[j][0], x0, x1);
            unpack2(acc[j][1], x2, x3);
            unsigned hA, lA, hB, lB;
            split2(x0, x1, hA, lA);
            split2(x2, x3, hB, lB);
            unsigned relb = (unsigned)(r0 + j) * 144u + (unsigned)c0 * 2u;
            *(uint2*)(sm + OFF_XHI + relb) = make_uint2(hA, hB);
            *(uint2*)(sm + OFF_XLO + relb) = make_uint2(lA, lB);
        }
    }

    size_t rowBase = (size_t)blk * 128;
    int wm = w & 1, wn = w >> 1;
    unsigned kA = ((l >> 4) & 1) * 8;
    unsigned rowA = (unsigned)(wm * 64 + (l & 7) + ((l >> 3) & 1) * 8);

    for (int p = 0; p < 2; p++) {
        __syncthreads();
        const float* B1 = p ? fb1 : bb1;
        const float* B2 = p ? fb2 : bb2;

        {
            float acc[4][4][4];
            #pragma unroll
            for (int a = 0; a < 4; a++)
                #pragma unroll
                for (int b = 0; b < 4; b++)
                    #pragma unroll
                    for (int c = 0; c < 4; c++) acc[a][b][c] = 0.f;

            unsigned aXhi = sb + OFF_XHI + rowA * 144 + kA * 2;
            unsigned aXlo = sb + OFF_XLO + rowA * 144 + kA * 2;
            const uint4* F1 = (const uint4*)gF1 + ((p * 4 + wn) * 4) * 4 * 32 + l;

            #pragma unroll
            for (int ki = 0; ki < 4; ki++) {
                unsigned kb = ki * 32;
                unsigned ah[4][4], al[4][4];
                uint4 bh[2], bl[2];
                #pragma unroll
                for (int mf = 0; mf < 4; mf++) {
                    ldm4(ah[mf], aXhi + mf * (16 * 144) + kb);
                    ldm4(al[mf], aXlo + mf * (16 * 144) + kb);
                }
                bh[0] = F1[(ki * 4 + 0) * 32];
                bh[1] = F1[(ki * 4 + 1) * 32];
                bl[0] = F1[(ki * 4 + 2) * 32];
                bl[1] = F1[(ki * 4 + 3) * 32];
                const unsigned* bhp = (const unsigned*)bh;
                const unsigned* blp = (const unsigned*)bl;
                #pragma unroll
                for (int mf = 0; mf < 4; mf++)
                    #pragma unroll
                    for (int nf = 0; nf < 4; nf++)
                        mma16816(acc[mf][nf], ah[mf], &bhp[nf * 2]);
                #pragma unroll
                for (int mf = 0; mf < 4; mf++)
                    #pragma unroll
                    for (int nf = 0; nf < 4; nf++)
                        mma16816(acc[mf][nf], ah[mf], &blp[nf * 2]);
                #pragma unroll
                for (int mf = 0; mf < 4; mf++)
                    #pragma unroll
                    for (int nf = 0; nf < 4; nf++)
                        mma16816(acc[mf][nf], al[mf], &bhp[nf * 2]);
            }
            int rbase = wm * 64 + (l >> 2);
            int ncol = 2 * (l & 3);
            #pragma unroll
            for (int nf = 0; nf < 4; nf++) {
                int n = wn * 32 + nf * 8 + ncol;
                float2 bv = *(const float2*)(B1 + n);
                #pragma unroll
                for (int mf = 0; mf < 4; mf++)
                    #pragma unroll
                    for (int half = 0; half < 2; half++) {
                        int r = rbase + mf * 16 + half * 8;
                        float v0 = fmaxf(acc[mf][nf][half * 2 + 0] + bv.x, 0.f);
                        float v1 = fmaxf(acc[mf][nf][half * 2 + 1] + bv.y, 0.f);
                        unsigned hp, lp;
                        split2(v0, v1, hp, lp);
                        unsigned off = (unsigned)r * 272u + (unsigned)n * 2u;
                        *(unsigned*)(sm + OFF_HHI + off) = hp;
                        *(unsigned*)(sm + OFF_HLO + off) = lp;
                    }
            }
        }
        __syncthreads();

        {
            float acc[4][2][4];
            #pragma unroll
            for (int a = 0; a < 4; a++)
                #pragma unroll
                for (int b = 0; b < 2; b++)
                    #pragma unroll
                    for (int c = 0; c < 4; c++) acc[a][b][c] = 0.f;

            unsigned aHhi = sb + OFF_HHI + rowA * 272 + kA * 2;
            unsigned aHlo = sb + OFF_HLO + rowA * 272 + kA * 2;
            const uint4* F2 = (const uint4*)gF2 + ((p * 4 + wn) * 8) * 2 * 32 + l;

            #pragma unroll
            for (int ki = 0; ki < 8; ki++) {
                unsigned kb = ki * 32;
                unsigned ah[4][4], al[4][4];
                uint4 bh4 = F2[(ki * 2 + 0) * 32];
                uint4 bl4 = F2[(ki * 2 + 1) * 32];
                const unsigned* bh = (const unsigned*)&bh4;
                const unsigned* bl = (const unsigned*)&bl4;
                #pragma unroll
                for (int mf = 0; mf < 4; mf++) {
                    ldm4(ah[mf], aHhi + mf * (16 * 272) + kb);
                    ldm4(al[mf], aHlo + mf * (16 * 272) + kb);
                }
                #pragma unroll
                for (int mf = 0; mf < 4; mf++)
                    #pragma unroll
                    for (int nf = 0; nf < 2; nf++)
                        mma16816(acc[mf][nf], ah[mf], &bh[nf * 2]);
                #pragma unroll
                for (int mf = 0; mf < 4; mf++)
                    #pragma unroll
                    for (int nf = 0; nf < 2; nf++)
                        mma16816(acc[mf][nf], ah[mf], &bl[nf * 2]);
                #pragma unroll
                for (int mf = 0; mf < 4; mf++)
                    #pragma unroll
                    for (int nf = 0; nf < 2; nf++)
                        mma16816(acc[mf][nf], al[mf], &bh[nf * 2]);
            }
            float* outp = out + (size_t)p * 33554432ull + rowBase * 64;
            int rbase = wm * 64 + (l >> 2);
            int ncol = 2 * (l & 3);
            #pragma unroll
            for (int nf = 0; nf < 2; nf++) {
                int n = wn * 16 + nf * 8 + ncol;
                float2 bv = *(const float2*)(B2 + n);
                #pragma unroll
                for (int mf = 0; mf < 4; mf++)
                    #pragma unroll
                    for (int half = 0; half < 2; half++) {
                        int r = rbase + mf * 16 + half * 8;
                        float2 val = make_float2(acc[mf][nf][half * 2 + 0] + bv.x,
                                                 acc[mf][nf][half * 2 + 1] + bv.y);
                        *(float2*)(outp + (size_t)r * 64 + n) = val;
                    }
            }
        }
    }
}

// ---------------------------------------------------------------------------
extern "C" void kernel_launch(void* const* d_in, const int* in_sizes, int n_in,
                              void* d_out, int out_size) {
    const float* x = (const float*)d_in[0];
    const float* w0 = (const float*)d_in[1];
    const float* w1 = (const float*)d_in[2];
    const float* w2 = (const float*)d_in[3];
    const float* w3 = (const float*)d_in[4];
    const float* bw1 = (const float*)d_in[5];
    const float* bb1 = (const float*)d_in[6];
    const float* bw2 = (const float*)d_in[7];
    const float* bb2 = (const float*)d_in[8];
    const float* fw1 = (const float*)d_in[9];
    const float* fb1 = (const float*)d_in[10];
    const float* fw2 = (const float*)d_in[11];
    const float* fb2 = (const float*)d_in[12];
    float* out = (float*)d_out;

    const int SM_PF = 71680;
    const int SM_K1 = 40960;
    const int SM_K2 = 49152;
    const int SM_K3B4 = 100352;
    cudaFuncSetAttribute(prep_frag, cudaFuncAttributeMaxDynamicSharedMemorySize, SM_PF);
    cudaFuncSetAttribute(k1_stageA, cudaFuncAttributeMaxDynamicSharedMemorySize, SM_K1);
    cudaFuncSetAttribute(k2_stageB, cudaFuncAttributeMaxDynamicSharedMemorySize, SM_K2);
    cudaFuncSetAttribute(k3b4_mix_inv, cudaFuncAttributeMaxDynamicSharedMemorySize, SM_K3B4);
    cudaFuncSetAttribute(k5_mma, cudaFuncAttributeMaxDynamicSharedMemorySize, SMEM_K5);

    prep_frag<<<2, 256, SM_PF>>>(bw1, fw1, bw2, fw2);
    prep_spec<<<256, 256>>>(w0, w1, w2, w3);
    prep_e<<<40, 256>>>();
    k1_stageA<<<NB * 128, 256, SM_K1>>>(x);
    k2_stageB<<<NB * 16, 256, SM_K2>>>();
    k3a_mix1<<<NB * 32, 256>>>();
    k3b4_mix_inv<<<NB * 16, 256, SM_K3B4>>>();
    k5_mma<<<NB * 128, 256, SMEM_K5>>>(bb1, bb2, fb1, fb2, out);
}

// round 16
// speedup vs baseline: 1.0359x; 1.0359x over previous
#include <cuda_runtime.h>
#include <cuda_bf16.h>
#include <math.h>

#define NB 32

// ---------------- device globals ----------------
__device__ float2 gA[NB * 16 * 128 * 64];  // [b][ky][m][i]
__device__ float2 gY[NB * 32 * 16 * 64];
__device__ float2 gT[NB * 32 * 16 * 64];
__device__ float2 gD[NB * 128 * 16 * 64];
// transposed spectral weights
__device__ float2 gW0t[65536], gW1t[65536], gW2t[65536], gW3t[65536];
// duplicated inverse-ky basis: E2[v*32+c] = {e,e}
__device__ __align__(16) float2 gE2[4096];
// packed twiddles: k1 [kg][n][4] {cos,-sin}; k2 [ug][m][4] {cos,sin}
__device__ __align__(16) float2 gTwK1p[4096];
__device__ __align__(16) float2 gTw2p[2048];
// pre-built mma B-fragments
__device__ __align__(16) unsigned gF1[16384];
__device__ __align__(16) unsigned gF2[16384];

// ---------------- helpers ----------------
typedef unsigned long long ull;
__device__ __forceinline__ ull pack2(float lo, float hi) {
    ull r;
    asm("mov.b64 %0, {%1,%2};" : "=l"(r) : "f"(lo), "f"(hi));
    return r;
}
__device__ __forceinline__ void unpack2(ull v, float& lo, float& hi) {
    asm("mov.b64 {%0,%1}, %2;" : "=f"(lo), "=f"(hi) : "l"(v));
}
__device__ __forceinline__ void ffma2(ull& d, ull a, ull b) {
    asm("fma.rn.f32x2 %0, %1, %2, %0;" : "+l"(d) : "l"(a), "l"(b));
}
__device__ __forceinline__ unsigned smem_u32(const void* p) {
    unsigned a;
    asm("{ .reg .u64 t; cvta.to.shared.u64 t, %1; cvt.u32.u64 %0, t; }" : "=r"(a) : "l"(p));
    return a;
}
__device__ __forceinline__ void ldm4(unsigned* r, unsigned addr) {
    asm volatile("ldmatrix.sync.aligned.m8n8.x4.shared.b16 {%0,%1,%2,%3}, [%4];"
                 : "=r"(r[0]), "=r"(r[1]), "=r"(r[2]), "=r"(r[3]) : "r"(addr));
}
__device__ __forceinline__ void mma16816(float* c, const unsigned* a, const unsigned* b) {
    asm volatile("mma.sync.aligned.m16n8k16.row.col.f32.bf16.bf16.f32 "
                 "{%0,%1,%2,%3}, {%4,%5,%6,%7}, {%8,%9}, {%0,%1,%2,%3};"
                 : "+f"(c[0]), "+f"(c[1]), "+f"(c[2]), "+f"(c[3])
                 : "r"(a[0]), "r"(a[1]), "r"(a[2]), "r"(a[3]), "r"(b[0]), "r"(b[1]));
}
__device__ __forceinline__ void split2(float v0, float v1, unsigned& hp, unsigned& lp) {
    asm("cvt.rn.bf16x2.f32 %0, %1, %2;" : "=r"(hp) : "f"(v1), "f"(v0));
    float h0 = __uint_as_float(hp << 16);
    float h1 = __uint_as_float(hp & 0xFFFF0000u);
    float l0 = v0 - h0, l1 = v1 - h1;
    asm("cvt.rn.bf16x2.f32 %0, %1, %2;" : "=r"(lp) : "f"(l1), "f"(l0));
}

// ---------------- prep: B-fragments via real ldmatrix ----------------
__global__ void prep_frag(const float* __restrict__ bw1, const float* __restrict__ fw1,
                          const float* __restrict__ bw2, const float* __restrict__ fw2) {
    extern __shared__ __align__(16) char ps[];
    int p = blockIdx.x, t = threadIdx.x, w = t >> 5, l = t & 31;
    const float* W1 = p ? fw1 : bw1;
    const float* W2 = p ? fw2 : bw2;
    for (int e = t; e < 9216; e += 256) {
        int n = e / 72, k = e % 72;
        float v = (k < 64) ? W1[k * 128 + n] : 0.f;
        __nv_bfloat16 hi = __float2bfloat16(v);
        __nv_bfloat16 lo = __float2bfloat16(v - __bfloat162float(hi));
        ((unsigned short*)(ps + 0))[e] = __bfloat16_as_ushort(hi);
        ((unsigned short*)(ps + 18432))[e] = __bfloat16_as_ushort(lo);
    }
    for (int e = t; e < 8704; e += 256) {
        int n = e / 136, k = e % 136;
        float v = (k < 128) ? W2[k * 64 + n] : 0.f;
        __nv_bfloat16 hi = __float2bfloat16(v);
        __nv_bfloat16 lo = __float2bfloat16(v - __bfloat162float(hi));
        ((unsigned short*)(ps + 36864))[e] = __bfloat16_as_ushort(hi);
        ((unsigned short*)(ps + 54272))[e] = __bfloat16_as_ushort(lo);
    }
    __syncthreads();
    unsigned sb = smem_u32(ps);
    unsigned kB = ((l >> 3) & 1) * 8;
    if (w < 4) {
        int wn = w;
        unsigned rowB = (unsigned)(wn * 32 + ((l >> 4) << 3) + (l & 7));
        for (int ki = 0; ki < 4; ki++)
            for (int term = 0; term < 2; term++)
                for (int h2 = 0; h2 < 2; h2++) {
                    unsigned r[4];
                    ldm4(r, sb + (term ? 18432u : 0u) + rowB * 144 + kB * 2 +
                            (unsigned)ki * 32 + (unsigned)h2 * (16 * 144));
                    ((uint4*)gF1)[((((p * 4 + wn) * 4 + ki) * 2 + term) * 2 + h2) * 32 + l] =
                        make_uint4(r[0], r[1], r[2], r[3]);
                }
    } else {
        int wn = w - 4;
        unsigned rowB = (unsigned)(wn * 16 + ((l >> 4) << 3) + (l & 7));
        for (int ki = 0; ki < 8; ki++)
            for (int term = 0; term < 2; term++) {
                unsigned r[4];
                ldm4(r, sb + (term ? 54272u : 36864u) + rowB * 272 + kB * 2 + (unsigned)ki * 32);
                ((uint4*)gF2)[(((p * 4 + wn) * 8 + ki) * 2 + term) * 32 + l] =
                    make_uint4(r[0], r[1], r[2], r[3]);
            }
    }
}

// ---------------- prep: transpose spectral weights (tiled, coalesced) ----------------
__global__ void prep_spec(const float* __restrict__ w0, const float* __restrict__ w1,
                          const float* __restrict__ w2, const float* __restrict__ w3) {
    __shared__ float2 tile[64][17];
    int wsel = blockIdx.x >> 6, tb = blockIdx.x & 63;
    const float2* src;
    float2* dst;
    switch (wsel) {
        case 0: src = (const float2*)w0; dst = gW0t; break;
        case 1: src = (const float2*)w1; dst = gW1t; break;
        case 2: src = (const float2*)w2; dst = gW2t; break;
        default: src = (const float2*)w3; dst = gW3t; break;
    }
    int t = threadIdx.x;
    for (int e = t; e < 1024; e += 256) {
        int ij = e >> 4, lx = e & 15;
        tile[ij][lx] = src[(tb * 64 + ij) * 16 + lx];
    }
    __syncthreads();
    for (int e = t; e < 1024; e += 256) {
        int lx = e >> 6, ij = e & 63;
        dst[lx * 4096 + tb * 64 + ij] = tile[ij][lx];
    }
}

// ---------------- prep: E table + packed twiddles ----------------
__global__ void prep_e() {
    int e = blockIdx.x * 256 + threadIdx.x;
    if (e < 4096) {
        int v = e >> 5, c = e & 31, k = c >> 1;
        float sv, cv;
        sincospif((float)(v * k) * (1.0f / 64.0f), &sv, &cv);
        float val = (c & 1) ? sv : cv;
        gE2[e] = make_float2(val, val);
    } else if (e < 8192) {
        int e2 = e - 4096;
        int kg = e2 >> 8, n = (e2 >> 2) & 63, j = e2 & 3;
        int ky = kg * 4 + j;
        float sv, cv;
        sincospif((float)(ky * n) * (1.0f / 64.0f), &sv, &cv);
        gTwK1p[e2] = make_float2(cv, -sv);
    } else if (e < 10240) {
        int e2 = e - 8192;
        int ug = e2 >> 9, m = (e2 >> 2) & 127, q = e2 & 3;
        int k = ug * 4 + q + 1;
        float sv, cv;
        sincospif((float)(k * m) * (1.0f / 64.0f), &sv, &cv);
        gTw2p[e2] = make_float2(cv, sv);
    }
}

// ---------------- K1: forward DFT along n (fold-on-load) ----------------
__global__ __launch_bounds__(256) void k1_stageA(const float* __restrict__ x) {
    extern __shared__ float smf[];
    float2* sd = (float2*)smf;
    float2* twk = (float2*)(smf + 8064);
    float* r064 = smf + 8064 + 2048;
    int bm = blockIdx.x, t = threadIdx.x;
    const float* xf = x + (size_t)bm * 8192;
    const float4* xg = (const float4*)xf;

    if (t < 64) r064[t] = xf[t];
    else if (t < 128) r064[t] = xf[4096 + (t - 64)];
    #pragma unroll
    for (int e = t; e < 512; e += 256) ((float4*)twk)[e] = ((const float4*)gTwK1p)[e];
    for (int e = t; e < 1008; e += 256) {
        int n = 1 + (e >> 4), i4 = e & 15;
        float4 a = xg[n * 16 + i4];
        float4 b = xg[(128 - n) * 16 + i4];
        float4* dst = (float4*)&sd[(n - 1) * 64 + i4 * 4];
        dst[0] = make_float4(a.x + b.x, a.x - b.x, a.y + b.y, a.y - b.y);
        dst[1] = make_float4(a.z + b.z, a.z - b.z, a.w + b.w, a.w - b.w);
    }
    __syncthreads();

    int i = t & 63, kg = t >> 6;
    int ky0 = kg * 4;
    float x0 = r064[i], x64 = r064[64 + i];
    const ull* sd2 = (const ull*)sd + i;
    const ulonglong2* twp = (const ulonglong2*)twk + kg * 128;
    ull a0 = pack2(x0 + x64, 0.f);
    ull a1 = pack2(x0 - x64, 0.f);
    ull a2 = pack2(x0 + x64, 0.f);
    ull a3 = pack2(x0 - x64, 0.f);
    #pragma unroll
    for (int n = 1; n <= 63; n++) {
        ull sdv = sd2[(n - 1) * 64];
        ulonglong2 t01 = twp[n * 2];
        ulonglong2 t23 = twp[n * 2 + 1];
        ffma2(a0, sdv, t01.x);
        ffma2(a1, sdv, t01.y);
        ffma2(a2, sdv, t23.x);
        ffma2(a3, sdv, t23.y);
    }
    int b = bm >> 7, m = bm & 127;
    float2* outp = gA + ((size_t)b * 16) * 8192 + (size_t)m * 64 + i;
    float lo, hi;
    unpack2(a0, lo, hi); outp[(size_t)(ky0 + 0) * 8192] = make_float2(lo, hi);
    unpack2(a1, lo, hi); outp[(size_t)(ky0 + 1) * 8192] = make_float2(lo, hi);
    unpack2(a2, lo, hi); outp[(size_t)(ky0 + 2) * 8192] = make_float2(lo, hi);
    unpack2(a3, lo, hi); outp[(size_t)(ky0 + 3) * 8192] = make_float2(lo, hi);
}

// ---------------- K2: forward DFT along m (two half-passes, 48KB smem) ----------------
__global__ __launch_bounds__(256) void k2_stageB() {
    extern __shared__ float2 sm2[];
    float2* As = sm2;
    float2* tw = sm2 + 4096;
    int blk = blockIdx.x, b = blk >> 4, ky = blk & 15, t = threadIdx.x;
    #pragma unroll
    for (int e = t; e < 1024; e += 256) ((float4*)tw)[e] = ((const float4*)gTw2p)[e];

    int i = t & 63, ug = t >> 6;
    ull acc12[4], acc34[4];
    #pragma unroll
    for (int q = 0; q < 4; q++) { acc12[q] = 0ull; acc34[q] = 0ull; }
    const ulonglong2* twp = (const ulonglong2*)tw + ug * 256;
    float sx = 0.f, sy = 0.f;

    const float4* src = (const float4*)(gA + (size_t)blk * 8192);
    #pragma unroll
    for (int ph = 0; ph < 2; ph++) {
        __syncthreads();
        #pragma unroll
        for (int e = t; e < 2048; e += 256) ((float4*)As)[e] = src[ph * 2048 + e];
        __syncthreads();
        #pragma unroll 4
        for (int mm = 0; mm < 64; mm++) {
            int m = ph * 64 + mm;
            float2 a = As[mm * 64 + i];
            ull axy = pack2(a.x, a.y), ayx = pack2(a.y, a.x);
            ulonglong2 t01 = twp[m * 2];
            ulonglong2 t23 = twp[m * 2 + 1];
            ffma2(acc12[0], axy, t01.x); ffma2(acc34[0], ayx, t01.x);
            ffma2(acc12[1], axy, t01.y); ffma2(acc34[1], ayx, t01.y);
            ffma2(acc12[2], axy, t23.x); ffma2(acc34[2], ayx, t23.x);
            ffma2(acc12[3], axy, t23.y); ffma2(acc34[3], ayx, t23.y);
            if (ug == 3) { sx += a.x; sy += a.y; }
        }
    }
    float2* yb = gY + (((size_t)b * 32) * 16 + ky) * 64 + i;
    #pragma unroll
    for (int q = 0; q < 4; q++) {
        int k = ug * 4 + q + 1;
        float u1, u2, u3, u4;
        unpack2(acc12[q], u1, u2);
        unpack2(acc34[q], u3, u4);
        if (k < 16) yb[(size_t)k * 1024] = make_float2(u1 + u2, u3 - u4);
        yb[(size_t)(32 - k) * 1024] = make_float2(u1 - u2, u3 + u4);
    }
    if (ug == 3) yb[0] = make_float2(sx, sy);
}

// ---------------- K3a ----------------
__global__ __launch_bounds__(256) void k3a_mix1() {
    __shared__ float4 Ys4[16 * 64];
    __shared__ float2 Was[64 * 64];
    int blk = blockIdx.x, s = blk & 31, lx = s & 15, t = threadIdx.x;
    const float2* wt = (s < 16) ? gW0t : gW2t;
    for (int e = t; e < 1024; e += 256) {
        float2 y = gY[(size_t)blk * 1024 + e];
        Ys4[e] = make_float4(y.x, y.y, -y.y, y.x);
    }
    for (int e = t; e < 4096; e += 256) Was[e] = wt[lx * 4096 + e];
    __syncthreads();
    int j = t & 63, kg = t >> 6;
    ull acc[4];
    #pragma unroll
    for (int q = 0; q < 4; q++) acc[q] = 0ull;
    for (int ii = 0; ii < 64; ii++) {
        float2 wv = Was[ii * 64 + j];
        ull wr2 = pack2(wv.x, wv.x), wi2 = pack2(wv.y, wv.y);
        #pragma unroll
        for (int q = 0; q < 4; q++) {
            const ull* y2 = (const ull*)&Ys4[(kg * 4 + q) * 64 + ii];
            ffma2(acc[q], wr2, y2[0]);
            ffma2(acc[q], wi2, y2[1]);
        }
    }
    #pragma unroll
    for (int q = 0; q < 4; q++) {
        float re, im;
        unpack2(acc[q], re, im);
        gT[(size_t)blk * 1024 + (kg * 4 + q) * 64 + j] = make_float2(re, im);
    }
}

// ---------------- K3b4 (fused): second channel mix + inverse DFT over kx ----------------
__global__ __launch_bounds__(256) void k3b4_mix_inv() {
    extern __shared__ __align__(16) char smb[];
    float4* Ts4 = (float4*)smb;
    float2* Wb0 = (float2*)(smb + 32768);
    float2* Wb1 = (float2*)(smb + 65536);
    float4* tab4 = (float4*)(smb + 98304);
    float2* Fs = (float2*)(smb + 32768);
    float4* PQ = (float4*)(smb + 49152);
    int blk = blockIdx.x, b = blk >> 4, ky = blk & 15, t = threadIdx.x;

    for (int e = t; e < 2048; e += 256) {
        int s_ = e >> 6, j = e & 63;
        float2 tv = gT[(((size_t)b * 32 + s_) * 16 + ky) * 64 + j];
        Ts4[e] = make_float4(tv.x, tv.y, -tv.y, tv.x);
    }
    for (int e = t; e < 4096; e += 256) {
        Wb0[e] = gW1t[ky * 4096 + e];
        Wb1[e] = gW3t[ky * 4096 + e];
    }
    if (t < 128) {
        float sv, cv;
        sincospif((float)t * (1.0f / 64.0f), &sv, &cv);
        tab4[t] = make_float4(cv, cv, sv, sv);
    }
    __syncthreads();

    int o = t & 63, sg = t >> 6;
    const float2* Wb = (sg < 2) ? Wb0 : Wb1;
    ull acc[8];
    #pragma unroll
    for (int q = 0; q < 8; q++) acc[q] = 0ull;
    for (int j = 0; j < 64; j++) {
        float2 wv = Wb[j * 64 + o];
        ull wr2 = pack2(wv.x, wv.x), wi2 = pack2(wv.y, wv.y);
        #pragma unroll
        for (int q = 0; q < 8; q++) {
            ulonglong2 tp = *(const ulonglong2*)&Ts4[(sg * 8 + q) * 64 + j];
            ffma2(acc[q], wr2, tp.x);
            ffma2(acc[q], wi2, tp.y);
        }
    }
    __syncthreads();
    #pragma unroll
    for (int q = 0; q < 8; q++) {
        int s_ = sg * 8 + q;
        float re, im;
        unpack2(acc[q], re, im);
        Fs[s_ * 64 + o] = make_float2(re, im);
    }
    __syncthreads();

    for (int e = t; e < 1024; e += 256) {
        int k = e >> 6, oo = e & 63;
        if (k == 0) {
            float2 f = Fs[16 * 64 + oo];
            PQ[oo] = make_float4(f.x, f.y, f.y, -f.x);
        } else {
            float2 fa = Fs[k * 64 + oo], fb = Fs[(32 - k) * 64 + oo];
            PQ[k * 64 + oo] = make_float4(fa.x + fb.x, fa.y + fb.y, -(fa.y - fb.y), fa.x - fb.x);
        }
    }
    __syncthreads();

    int ug = t >> 6;
    float2 F0 = Fs[o];
    float4 pq[16];
    #pragma unroll
    for (int k = 0; k < 16; k++) pq[k] = PQ[k * 64 + o];

    for (int q = 0; q < 32; q++) {
        int u = ug * 32 + q;
        ull acc2 = pack2(F0.x, F0.y);
        int idx = u;
        #pragma unroll
        for (int k = 1; k < 16; k++) {
            const ull* cs = (const ull*)&tab4[idx];
            ffma2(acc2, cs[0], ((const ull*)&pq[k])[0]);
            ffma2(acc2, cs[1], ((const ull*)&pq[k])[1]);
            idx = (idx + u) & 127;
        }
        {
            const ull* cs = (const ull*)&tab4[(16 * u) & 127];
            ffma2(acc2, cs[0], ((const ull*)&pq[0])[0]);
            ffma2(acc2, cs[1], ((const ull*)&pq[0])[1]);
        }
        float re, im;
        unpack2(acc2, re, im);
        gD[(((size_t)b * 128 + u) * 16 + ky) * 64 + o] = make_float2(re, im);
    }
}

// ---------------- K5: inverse ky + both MLPs (W frags from global, E2 staged in smem) ----------------
#define OFF_XHI   0u
#define OFF_XLO   18432u
#define OFF_HHI   36864u
#define OFF_HLO   71680u
#define SMEM_K5   106496

__global__ __launch_bounds__(256, 2) void k5_mma(
    const float* __restrict__ bb1, const float* __restrict__ bb2,
    const float* __restrict__ fb1, const float* __restrict__ fb2,
    float* __restrict__ out) {
    extern __shared__ __align__(16) char sm[];
    unsigned sb = smem_u32(sm);
    int t = threadIdx.x, w = t >> 5, l = t & 31;
    int blk = blockIdx.x;

    // stage-1 scratch (aliases H region): E2 (32KB) + Dp (8KB)
    float2* E2 = (float2*)(sm + OFF_HHI);
    float* Dp = (float*)(sm + OFF_HHI + 32768);
    for (int e = t; e < 2048; e += 256)
        ((float4*)E2)[e] = ((const float4*)gE2)[e];
    for (int e = t; e < 1024; e += 256) {
        int ky = e >> 6, o = e & 63;
        float2 d = gD[(size_t)blk * 1024 + e];
        float sc = (ky ? 2.0f : 1.0f) * (1.0f / 16384.0f);
        Dp[(2 * ky) * 64 + o] = d.x * sc;
        Dp[(2 * ky + 1) * 64 + o] = -d.y * sc;
    }
    __syncthreads();

    {
        int rg = t >> 4, cg = t & 15;
        int r0 = rg * 8, c0 = cg * 4;
        ull acc[8][2];
        #pragma unroll
        for (int j = 0; j < 8; j++) { acc[j][0] = 0ull; acc[j][1] = 0ull; }
        const ull* E2u = (const ull*)E2;
        for (int c = 0; c < 32; c++) {
            ulonglong2 dd = *(const ulonglong2*)&Dp[c * 64 + c0];
            #pragma unroll
            for (int j = 0; j < 8; j++) {
                ull e2 = E2u[(r0 + j) * 32 + c];
                ffma2(acc[j][0], e2, dd.x);
                ffma2(acc[j][1], e2, dd.y);
            }
        }
        #pragma unroll
        for (int j = 0; j < 8; j++) {
            float x0, x1, x2, x3;
            unpack2(acc[j][0], x0, x1);
            unpack2(acc[j][1], x2, x3);
            unsigned hA, lA, hB, lB;
            split2(x0, x1, hA, lA);
            split2(x2, x3, hB, lB);
            unsigned relb = (unsigned)(r0 + j) * 144u + (unsigned)c0 * 2u;
            *(uint2*)(sm + OFF_XHI + relb) = make_uint2(hA, hB);
            *(uint2*)(sm + OFF_XLO + relb) = make_uint2(lA, lB);
        }
    }

    size_t rowBase = (size_t)blk * 128;
    int wm = w & 1, wn = w >> 1;
    unsigned kA = ((l >> 4) & 1) * 8;
    unsigned rowA = (unsigned)(wm * 64 + (l & 7) + ((l >> 3) & 1) * 8);

    for (int p = 0; p < 2; p++) {
        __syncthreads();
        const float* B1 = p ? fb1 : bb1;
        const float* B2 = p ? fb2 : bb2;

        {
            float acc[4][4][4];
            #pragma unroll
            for (int a = 0; a < 4; a++)
                #pragma unroll
                for (int b = 0; b < 4; b++)
                    #pragma unroll
                    for (int c = 0; c < 4; c++) acc[a][b][c] = 0.f;

            unsigned aXhi = sb + OFF_XHI + rowA * 144 + kA * 2;
            unsigned aXlo = sb + OFF_XLO + rowA * 144 + kA * 2;
            const uint4* F1 = (const uint4*)gF1 + ((p * 4 + wn) * 4) * 4 * 32 + l;

            #pragma unroll
            for (int ki = 0; ki < 4; ki++) {
                unsigned kb = ki * 32;
                unsigned ah[4][4], al[4][4];
                uint4 bh[2], bl[2];
                #pragma unroll
                for (int mf = 0; mf < 4; mf++) {
                    ldm4(ah[mf], aXhi + mf * (16 * 144) + kb);
                    ldm4(al[mf], aXlo + mf * (16 * 144) + kb);
                }
                bh[0] = F1[(ki * 4 + 0) * 32];
                bh[1] = F1[(ki * 4 + 1) * 32];
                bl[0] = F1[(ki * 4 + 2) * 32];
                bl[1] = F1[(ki * 4 + 3) * 32];
                const unsigned* bhp = (const unsigned*)bh;
                const unsigned* blp = (const unsigned*)bl;
                #pragma unroll
                for (int mf = 0; mf < 4; mf++)
                    #pragma unroll
                    for (int nf = 0; nf < 4; nf++)
                        mma16816(acc[mf][nf], ah[mf], &bhp[nf * 2]);
                #pragma unroll
                for (int mf = 0; mf < 4; mf++)
                    #pragma unroll
                    for (int nf = 0; nf < 4; nf++)
                        mma16816(acc[mf][nf], ah[mf], &blp[nf * 2]);
                #pragma unroll
                for (int mf = 0; mf < 4; mf++)
                    #pragma unroll
                    for (int nf = 0; nf < 4; nf++)
                        mma16816(acc[mf][nf], al[mf], &bhp[nf * 2]);
            }
            int rbase = wm * 64 + (l >> 2);
            int ncol = 2 * (l & 3);
            #pragma unroll
            for (int nf = 0; nf < 4; nf++) {
                int n = wn * 32 + nf * 8 + ncol;
                float2 bv = *(const float2*)(B1 + n);
                #pragma unroll
                for (int mf = 0; mf < 4; mf++)
                    #pragma unroll
                    for (int half = 0; half < 2; half++) {
                        int r = rbase + mf * 16 + half * 8;
                        float v0 = fmaxf(acc[mf][nf][half * 2 + 0] + bv.x, 0.f);
                        float v1 = fmaxf(acc[mf][nf][half * 2 + 1] + bv.y, 0.f);
                        unsigned hp, lp;
                        split2(v0, v1, hp, lp);
                        unsigned off = (unsigned)r * 272u + (unsigned)n * 2u;
                        *(unsigned*)(sm + OFF_HHI + off) = hp;
                        *(unsigned*)(sm + OFF_HLO + off) = lp;
                    }
            }
        }
        __syncthreads();

        {
            float acc[4][2][4];
            #pragma unroll
            for (int a = 0; a < 4; a++)
                #pragma unroll
                for (int b = 0; b < 2; b++)
                    #pragma unroll
                    for (int c = 0; c < 4; c++) acc[a][b][c] = 0.f;

            unsigned aHhi = sb + OFF_HHI + rowA * 272 + kA * 2;
            unsigned aHlo = sb + OFF_HLO + rowA * 272 + kA * 2;
            const uint4* F2 = (const uint4*)gF2 + ((p * 4 + wn) * 8) * 2 * 32 + l;

            #pragma unroll
            for (int ki = 0; ki < 8; ki++) {
                unsigned kb = ki * 32;
                unsigned ah[4][4], al[4][4];
                uint4 bh4 = F2[(ki * 2 + 0) * 32];
                uint4 bl4 = F2[(ki * 2 + 1) * 32];
                const unsigned* bh = (const unsigned*)&bh4;
                const unsigned* bl = (const unsigned*)&bl4;
                #pragma unroll
                for (int mf = 0; mf < 4; mf++) {
                    ldm4(ah[mf], aHhi + mf * (16 * 272) + kb);
                    ldm4(al[mf], aHlo + mf * (16 * 272) + kb);
                }
                #pragma unroll
                for (int mf = 0; mf < 4; mf++)
                    #pragma unroll
                    for (int nf = 0; nf < 2; nf++)
                        mma16816(acc[mf][nf], ah[mf], &bh[nf * 2]);
                #pragma unroll
                for (int mf = 0; mf < 4; mf++)
                    #pragma unroll
                    for (int nf = 0; nf < 2; nf++)
                        mma16816(acc[mf][nf], ah[mf], &bl[nf * 2]);
                #pragma unroll
                for (int mf = 0; mf < 4; mf++)
                    #pragma unroll
                    for (int nf = 0; nf < 2; nf++)
                        mma16816(acc[mf][nf], al[mf], &bh[nf * 2]);
            }
            float* outp = out + (size_t)p * 33554432ull + rowBase * 64;
            int rbase = wm * 64 + (l >> 2);
            int ncol = 2 * (l & 3);
            #pragma unroll
            for (int nf = 0; nf < 2; nf++) {
                int n = wn * 16 + nf * 8 + ncol;
                float2 bv = *(const float2*)(B2 + n);
                #pragma unroll
                for (int mf = 0; mf < 4; mf++)
                    #pragma unroll
                    for (int half = 0; half < 2; half++) {
                        int r = rbase + mf * 16 + half * 8;
                        float2 val = make_float2(acc[mf][nf][half * 2 + 0] + bv.x,
                                                 acc[mf][nf][half * 2 + 1] + bv.y);
                        *(float2*)(outp + (size_t)r * 64 + n) = val;
                    }
            }
        }
    }
}

// ---------------------------------------------------------------------------
extern "C" void kernel_launch(void* const* d_in, const int* in_sizes, int n_in,
                              void* d_out, int out_size) {
    const float* x = (const float*)d_in[0];
    const float* w0 = (const float*)d_in[1];
    const float* w1 = (const float*)d_in[2];
    const float* w2 = (const float*)d_in[3];
    const float* w3 = (const float*)d_in[4];
    const float* bw1 = (const float*)d_in[5];
    const float* bb1 = (const float*)d_in[6];
    const float* bw2 = (const float*)d_in[7];
    const float* bb2 = (const float*)d_in[8];
    const float* fw1 = (const float*)d_in[9];
    const float* fb1 = (const float*)d_in[10];
    const float* fw2 = (const float*)d_in[11];
    const float* fb2 = (const float*)d_in[12];
    float* out = (float*)d_out;

    const int SM_PF = 71680;
    const int SM_K1 = 40960;
    const int SM_K2 = 49152;
    const int SM_K3B4 = 100352;
    cudaFuncSetAttribute(prep_frag, cudaFuncAttributeMaxDynamicSharedMemorySize, SM_PF);
    cudaFuncSetAttribute(k1_stageA, cudaFuncAttributeMaxDynamicSharedMemorySize, SM_K1);
    cudaFuncSetAttribute(k2_stageB, cudaFuncAttributeMaxDynamicSharedMemorySize, SM_K2);
    cudaFuncSetAttribute(k3b4_mix_inv, cudaFuncAttributeMaxDynamicSharedMemorySize, SM_K3B4);
    cudaFuncSetAttribute(k5_mma, cudaFuncAttributeMaxDynamicSharedMemorySize, SMEM_K5);

    prep_frag<<<2, 256, SM_PF>>>(bw1, fw1, bw2, fw2);
    prep_spec<<<256, 256>>>(w0, w1, w2, w3);
    prep_e<<<40, 256>>>();
    k1_stageA<<<NB * 128, 256, SM_K1>>>(x);
    k2_stageB<<<NB * 16, 256, SM_K2>>>();
    k3a_mix1<<<NB * 32, 256>>>();
    k3b4_mix_inv<<<NB * 16, 256, SM_K3B4>>>();
    k5_mma<<<NB * 128, 256, SMEM_K5>>>(bb1, bb2, fb1, fb2, out);
}

// round 17
// speedup vs baseline: 1.0463x; 1.0100x over previous
#include <cuda_runtime.h>
#include <cuda_bf16.h>
#include <math.h>

#define NB 32

// ---------------- device globals ----------------
__device__ float2 gA[NB * 16 * 128 * 64];  // [b][ky][m][i]
__device__ float2 gY[NB * 32 * 16 * 64];
__device__ float2 gT[NB * 32 * 16 * 64];
__device__ float2 gD[NB * 128 * 16 * 64];
// transposed spectral weights (k3b4 uses w1/w3 halves)
__device__ float2 gW0t[65536], gW1t[65536], gW2t[65536], gW3t[65536];
// duplicated inverse-ky basis: E2[v*32+c] = {e,e}
__device__ __align__(16) float2 gE2[4096];
// packed twiddles
__device__ __align__(16) float2 gTwK1p[4096];
__device__ __align__(16) float2 gTw2p[2048];
// pre-built mma B-fragments (MLP)
__device__ __align__(16) unsigned gF1[16384];
__device__ __align__(16) unsigned gF2[16384];
// pre-built k3a spectral B-fragments: [s][nfp=8][ki=8][term=2][lane=32] uint4
__device__ __align__(16) uint4 gFS1[32 * 8 * 8 * 2 * 32];

// ---------------- helpers ----------------
typedef unsigned long long ull;
__device__ __forceinline__ ull pack2(float lo, float hi) {
    ull r;
    asm("mov.b64 %0, {%1,%2};" : "=l"(r) : "f"(lo), "f"(hi));
    return r;
}
__device__ __forceinline__ void unpack2(ull v, float& lo, float& hi) {
    asm("mov.b64 {%0,%1}, %2;" : "=f"(lo), "=f"(hi) : "l"(v));
}
__device__ __forceinline__ void ffma2(ull& d, ull a, ull b) {
    asm("fma.rn.f32x2 %0, %1, %2, %0;" : "+l"(d) : "l"(a), "l"(b));
}
__device__ __forceinline__ unsigned smem_u32(const void* p) {
    unsigned a;
    asm("{ .reg .u64 t; cvta.to.shared.u64 t, %1; cvt.u32.u64 %0, t; }" : "=r"(a) : "l"(p));
    return a;
}
__device__ __forceinline__ void ldm4(unsigned* r, unsigned addr) {
    asm volatile("ldmatrix.sync.aligned.m8n8.x4.shared.b16 {%0,%1,%2,%3}, [%4];"
                 : "=r"(r[0]), "=r"(r[1]), "=r"(r[2]), "=r"(r[3]) : "r"(addr));
}
__device__ __forceinline__ void mma16816(float* c, const unsigned* a, const unsigned* b) {
    asm volatile("mma.sync.aligned.m16n8k16.row.col.f32.bf16.bf16.f32 "
                 "{%0,%1,%2,%3}, {%4,%5,%6,%7}, {%8,%9}, {%0,%1,%2,%3};"
                 : "+f"(c[0]), "+f"(c[1]), "+f"(c[2]), "+f"(c[3])
                 : "r"(a[0]), "r"(a[1]), "r"(a[2]), "r"(a[3]), "r"(b[0]), "r"(b[1]));
}
__device__ __forceinline__ void split2(float v0, float v1, unsigned& hp, unsigned& lp) {
    asm("cvt.rn.bf16x2.f32 %0, %1, %2;" : "=r"(hp) : "f"(v1), "f"(v0));
    float h0 = __uint_as_float(hp << 16);
    float h1 = __uint_as_float(hp & 0xFFFF0000u);
    float l0 = v0 - h0, l1 = v1 - h1;
    asm("cvt.rn.bf16x2.f32 %0, %1, %2;" : "=r"(lp) : "f"(l1), "f"(l0));
}

// ---------------- prep: MLP B-fragments via real ldmatrix ----------------
__global__ void prep_frag(const float* __restrict__ bw1, const float* __restrict__ fw1,
                          const float* __restrict__ bw2, const float* __restrict__ fw2) {
    extern __shared__ __align__(16) char ps[];
    int p = blockIdx.x, t = threadIdx.x, w = t >> 5, l = t & 31;
    const float* W1 = p ? fw1 : bw1;
    const float* W2 = p ? fw2 : bw2;
    for (int e = t; e < 9216; e += 256) {
        int n = e / 72, k = e % 72;
        float v = (k < 64) ? W1[k * 128 + n] : 0.f;
        __nv_bfloat16 hi = __float2bfloat16(v);
        __nv_bfloat16 lo = __float2bfloat16(v - __bfloat162float(hi));
        ((unsigned short*)(ps + 0))[e] = __bfloat16_as_ushort(hi);
        ((unsigned short*)(ps + 18432))[e] = __bfloat16_as_ushort(lo);
    }
    for (int e = t; e < 8704; e += 256) {
        int n = e / 136, k = e % 136;
        float v = (k < 128) ? W2[k * 64 + n] : 0.f;
        __nv_bfloat16 hi = __float2bfloat16(v);
        __nv_bfloat16 lo = __float2bfloat16(v - __bfloat162float(hi));
        ((unsigned short*)(ps + 36864))[e] = __bfloat16_as_ushort(hi);
        ((unsigned short*)(ps + 54272))[e] = __bfloat16_as_ushort(lo);
    }
    __syncthreads();
    unsigned sb = smem_u32(ps);
    unsigned kB = ((l >> 3) & 1) * 8;
    if (w < 4) {
        int wn = w;
        unsigned rowB = (unsigned)(wn * 32 + ((l >> 4) << 3) + (l & 7));
        for (int ki = 0; ki < 4; ki++)
            for (int term = 0; term < 2; term++)
                for (int h2 = 0; h2 < 2; h2++) {
                    unsigned r[4];
                    ldm4(r, sb + (term ? 18432u : 0u) + rowB * 144 + kB * 2 +
                            (unsigned)ki * 32 + (unsigned)h2 * (16 * 144));
                    ((uint4*)gF1)[((((p * 4 + wn) * 4 + ki) * 2 + term) * 2 + h2) * 32 + l] =
                        make_uint4(r[0], r[1], r[2], r[3]);
                }
    } else {
        int wn = w - 4;
        unsigned rowB = (unsigned)(wn * 16 + ((l >> 4) << 3) + (l & 7));
        for (int ki = 0; ki < 8; ki++)
            for (int term = 0; term < 2; term++) {
                unsigned r[4];
                ldm4(r, sb + (term ? 54272u : 36864u) + rowB * 272 + kB * 2 + (unsigned)ki * 32);
                ((uint4*)gF2)[(((p * 4 + wn) * 8 + ki) * 2 + term) * 32 + l] =
                    make_uint4(r[0], r[1], r[2], r[3]);
            }
    }
}

// ---------------- prep: k3a spectral B-fragments ----------------
// grid 32 (s variants). Real embedding of complex W: row n=2j:{Wr,-Wi}, n=2j+1:{Wi,Wr}
// smem: hi image [128n][136k] (34816 B) @0, lo @34816 -> 69632 B
__global__ void prep_k3a(const float* __restrict__ w0, const float* __restrict__ w2) {
    extern __shared__ __align__(16) char ks[];
    int s = blockIdx.x, lx = s & 15, t = threadIdx.x, w = t >> 5, l = t & 31;
    const float2* wsrc = (const float2*)((s < 16) ? w0 : w2);
    for (int e = t; e < 4096; e += 256) {
        int i = e >> 6, j = e & 63;
        float2 wv = wsrc[e * 16 + lx];  // w[(i*64+j)*16+lx] = {Wr, Wi}
        unsigned hA, lA, hB, lB;
        split2(wv.x, -wv.y, hA, lA);
        split2(wv.y, wv.x, hB, lB);
        *(unsigned*)(ks + (2 * j) * 272 + 4 * i) = hA;
        *(unsigned*)(ks + 34816 + (2 * j) * 272 + 4 * i) = lA;
        *(unsigned*)(ks + (2 * j + 1) * 272 + 4 * i) = hB;
        *(unsigned*)(ks + 34816 + (2 * j + 1) * 272 + 4 * i) = lB;
    }
    __syncthreads();
    unsigned sb = smem_u32(ks);
    unsigned rowB = (unsigned)(w * 16 + ((l >> 4) << 3) + (l & 7));
    unsigned kB = ((l >> 3) & 1) * 8;
    for (int ki = 0; ki < 8; ki++)
        for (int term = 0; term < 2; term++) {
            unsigned r[4];
            ldm4(r, sb + (term ? 34816u : 0u) + rowB * 272 + kB * 2 + (unsigned)ki * 32);
            gFS1[(((s * 8 + w) * 8 + ki) * 2 + term) * 32 + l] =
                make_uint4(r[0], r[1], r[2], r[3]);
        }
}

// ---------------- prep: transpose spectral weights (tiled, coalesced) ----------------
__global__ void prep_spec(const float* __restrict__ w0, const float* __restrict__ w1,
                          const float* __restrict__ w2, const float* __restrict__ w3) {
    __shared__ float2 tile[64][17];
    int wsel = blockIdx.x >> 6, tb = blockIdx.x & 63;
    const float2* src;
    float2* dst;
    switch (wsel) {
        case 0: src = (const float2*)w0; dst = gW0t; break;
        case 1: src = (const float2*)w1; dst = gW1t; break;
        case 2: src = (const float2*)w2; dst = gW2t; break;
        default: src = (const float2*)w3; dst = gW3t; break;
    }
    int t = threadIdx.x;
    for (int e = t; e < 1024; e += 256) {
        int ij = e >> 4, lx = e & 15;
        tile[ij][lx] = src[(tb * 64 + ij) * 16 + lx];
    }
    __syncthreads();
    for (int e = t; e < 1024; e += 256) {
        int lx = e >> 6, ij = e & 63;
        dst[lx * 4096 + tb * 64 + ij] = tile[ij][lx];
    }
}

// ---------------- prep: E table + packed twiddles ----------------
__global__ void prep_e() {
    int e = blockIdx.x * 256 + threadIdx.x;
    if (e < 4096) {
        int v = e >> 5, c = e & 31, k = c >> 1;
        float sv, cv;
        sincospif((float)(v * k) * (1.0f / 64.0f), &sv, &cv);
        float val = (c & 1) ? sv : cv;
        gE2[e] = make_float2(val, val);
    } else if (e < 8192) {
        int e2 = e - 4096;
        int kg = e2 >> 8, n = (e2 >> 2) & 63, j = e2 & 3;
        int ky = kg * 4 + j;
        float sv, cv;
        sincospif((float)(ky * n) * (1.0f / 64.0f), &sv, &cv);
        gTwK1p[e2] = make_float2(cv, -sv);
    } else if (e < 10240) {
        int e2 = e - 8192;
        int ug = e2 >> 9, m = (e2 >> 2) & 127, q = e2 & 3;
        int k = ug * 4 + q + 1;
        float sv, cv;
        sincospif((float)(k * m) * (1.0f / 64.0f), &sv, &cv);
        gTw2p[e2] = make_float2(cv, sv);
    }
}

// ---------------- K1: forward DFT along n (fold-on-load) ----------------
__global__ __launch_bounds__(256) void k1_stageA(const float* __restrict__ x) {
    extern __shared__ float smf[];
    float2* sd = (float2*)smf;
    float2* twk = (float2*)(smf + 8064);
    float* r064 = smf + 8064 + 2048;
    int bm = blockIdx.x, t = threadIdx.x;
    const float* xf = x + (size_t)bm * 8192;
    const float4* xg = (const float4*)xf;

    if (t < 64) r064[t] = xf[t];
    else if (t < 128) r064[t] = xf[4096 + (t - 64)];
    #pragma unroll
    for (int e = t; e < 512; e += 256) ((float4*)twk)[e] = ((const float4*)gTwK1p)[e];
    for (int e = t; e < 1008; e += 256) {
        int n = 1 + (e >> 4), i4 = e & 15;
        float4 a = xg[n * 16 + i4];
        float4 b = xg[(128 - n) * 16 + i4];
        float4* dst = (float4*)&sd[(n - 1) * 64 + i4 * 4];
        dst[0] = make_float4(a.x + b.x, a.x - b.x, a.y + b.y, a.y - b.y);
        dst[1] = make_float4(a.z + b.z, a.z - b.z, a.w + b.w, a.w - b.w);
    }
    __syncthreads();

    int i = t & 63, kg = t >> 6;
    int ky0 = kg * 4;
    float x0 = r064[i], x64 = r064[64 + i];
    const ull* sd2 = (const ull*)sd + i;
    const ulonglong2* twp = (const ulonglong2*)twk + kg * 128;
    ull a0 = pack2(x0 + x64, 0.f);
    ull a1 = pack2(x0 - x64, 0.f);
    ull a2 = pack2(x0 + x64, 0.f);
    ull a3 = pack2(x0 - x64, 0.f);
    #pragma unroll
    for (int n = 1; n <= 63; n++) {
        ull sdv = sd2[(n - 1) * 64];
        ulonglong2 t01 = twp[n * 2];
        ulonglong2 t23 = twp[n * 2 + 1];
        ffma2(a0, sdv, t01.x);
        ffma2(a1, sdv, t01.y);
        ffma2(a2, sdv, t23.x);
        ffma2(a3, sdv, t23.y);
    }
    int b = bm >> 7, m = bm & 127;
    float2* outp = gA + ((size_t)b * 16) * 8192 + (size_t)m * 64 + i;
    float lo, hi;
    unpack2(a0, lo, hi); outp[(size_t)(ky0 + 0) * 8192] = make_float2(lo, hi);
    unpack2(a1, lo, hi); outp[(size_t)(ky0 + 1) * 8192] = make_float2(lo, hi);
    unpack2(a2, lo, hi); outp[(size_t)(ky0 + 2) * 8192] = make_float2(lo, hi);
    unpack2(a3, lo, hi); outp[(size_t)(ky0 + 3) * 8192] = make_float2(lo, hi);
}

// ---------------- K2: forward DFT along m (two half-passes, 48KB smem) ----------------
__global__ __launch_bounds__(256) void k2_stageB() {
    extern __shared__ float2 sm2[];
    float2* As = sm2;
    float2* tw = sm2 + 4096;
    int blk = blockIdx.x, b = blk >> 4, ky = blk & 15, t = threadIdx.x;
    #pragma unroll
    for (int e = t; e < 1024; e += 256) ((float4*)tw)[e] = ((const float4*)gTw2p)[e];

    int i = t & 63, ug = t >> 6;
    ull acc12[4], acc34[4];
    #pragma unroll
    for (int q = 0; q < 4; q++) { acc12[q] = 0ull; acc34[q] = 0ull; }
    const ulonglong2* twp = (const ulonglong2*)tw + ug * 256;
    float sx = 0.f, sy = 0.f;

    const float4* src = (const float4*)(gA + (size_t)blk * 8192);
    #pragma unroll
    for (int ph = 0; ph < 2; ph++) {
        __syncthreads();
        #pragma unroll
        for (int e = t; e < 2048; e += 256) ((float4*)As)[e] = src[ph * 2048 + e];
        __syncthreads();
        #pragma unroll 4
        for (int mm = 0; mm < 64; mm++) {
            int m = ph * 64 + mm;
            float2 a = As[mm * 64 + i];
            ull axy = pack2(a.x, a.y), ayx = pack2(a.y, a.x);
            ulonglong2 t01 = twp[m * 2];
            ulonglong2 t23 = twp[m * 2 + 1];
            ffma2(acc12[0], axy, t01.x); ffma2(acc34[0], ayx, t01.x);
            ffma2(acc12[1], axy, t01.y); ffma2(acc34[1], ayx, t01.y);
            ffma2(acc12[2], axy, t23.x); ffma2(acc34[2], ayx, t23.x);
            ffma2(acc12[3], axy, t23.y); ffma2(acc34[3], ayx, t23.y);
            if (ug == 3) { sx += a.x; sy += a.y; }
        }
    }
    float2* yb = gY + (((size_t)b * 32) * 16 + ky) * 64 + i;
    #pragma unroll
    for (int q = 0; q < 4; q++) {
        int k = ug * 4 + q + 1;
        float u1, u2, u3, u4;
        unpack2(acc12[q], u1, u2);
        unpack2(acc34[q], u3, u4);
        if (k < 16) yb[(size_t)k * 1024] = make_float2(u1 + u2, u3 - u4);
        yb[(size_t)(32 - k) * 1024] = make_float2(u1 - u2, u3 + u4);
    }
    if (ug == 3) yb[0] = make_float2(sx, sy);
}

// ---------------- K3a via mma: T[16ky,128n] = A(Y)[16,128] @ B(W)[128,128] ----------------
// grid 1024 = b*32+s, 256 thr. smem: A-hi [16][136] @0 (4352B), A-lo @4352.
__global__ __launch_bounds__(256) void k3a_mma() {
    __shared__ __align__(16) char ys[8704];
    int blk = blockIdx.x, s = blk & 31, t = threadIdx.x, w = t >> 5, l = t & 31;
    for (int e = t; e < 1024; e += 256) {
        int ky = e >> 6, i = e & 63;
        float2 y = gY[(size_t)blk * 1024 + e];
        unsigned hp, lp;
        split2(y.x, y.y, hp, lp);
        *(unsigned*)(ys + ky * 272 + 4 * i) = hp;
        *(unsigned*)(ys + 4352 + ky * 272 + 4 * i) = lp;
    }
    __syncthreads();
    unsigned sb = smem_u32(ys);
    unsigned rowA = (unsigned)((l & 7) + ((l >> 3) & 1) * 8);
    unsigned kA = ((l >> 4) & 1) * 8;
    unsigned aHi = sb + rowA * 272 + kA * 2;
    unsigned aLo = sb + 4352 + rowA * 272 + kA * 2;
    const uint4* FS = gFS1 + ((s * 8 + w) * 8) * 2 * 32 + l;

    float acc[2][4];
    #pragma unroll
    for (int nf = 0; nf < 2; nf++)
        #pragma unroll
        for (int c = 0; c < 4; c++) acc[nf][c] = 0.f;

    #pragma unroll
    for (int ki = 0; ki < 8; ki++) {
        unsigned ah[4], al[4];
        ldm4(ah, aHi + ki * 32);
        ldm4(al, aLo + ki * 32);
        uint4 bh4 = FS[(ki * 2 + 0) * 32];
        uint4 bl4 = FS[(ki * 2 + 1) * 32];
        const unsigned* bh = (const unsigned*)&bh4;
        const unsigned* bl = (const unsigned*)&bl4;
        #pragma unroll
        for (int nf = 0; nf < 2; nf++) mma16816(acc[nf], ah, &bh[nf * 2]);
        #pragma unroll
        for (int nf = 0; nf < 2; nf++) mma16816(acc[nf], ah, &bl[nf * 2]);
        #pragma unroll
        for (int nf = 0; nf < 2; nf++) mma16816(acc[nf], al, &bh[nf * 2]);
    }
    // epilogue: rows ky = l>>2 (+8); cols n = w*16 + nf*8 + 2*(l&3) -> j = n>>1
    float2* dst = gT + (size_t)blk * 1024;
    #pragma unroll
    for (int nf = 0; nf < 2; nf++) {
        int j = w * 8 + nf * 4 + (l & 3);
        dst[(l >> 2) * 64 + j] = make_float2(acc[nf][0], acc[nf][1]);
        dst[((l >> 2) + 8) * 64 + j] = make_float2(acc[nf][2], acc[nf][3]);
    }
}

// ---------------- K3b4 (fused): second channel mix + inverse DFT over kx ----------------
__global__ __launch_bounds__(256) void k3b4_mix_inv() {
    extern __shared__ __align__(16) char smb[];
    float4* Ts4 = (float4*)smb;
    float2* Wb0 = (float2*)(smb + 32768);
    float2* Wb1 = (float2*)(smb + 65536);
    float4* tab4 = (float4*)(smb + 98304);
    float2* Fs = (float2*)(smb + 32768);
    float4* PQ = (float4*)(smb + 49152);
    int blk = blockIdx.x, b = blk >> 4, ky = blk & 15, t = threadIdx.x;

    for (int e = t; e < 2048; e += 256) {
        int s_ = e >> 6, j = e & 63;
        float2 tv = gT[(((size_t)b * 32 + s_) * 16 + ky) * 64 + j];
        Ts4[e] = make_float4(tv.x, tv.y, -tv.y, tv.x);
    }
    for (int e = t; e < 4096; e += 256) {
        Wb0[e] = gW1t[ky * 4096 + e];
        Wb1[e] = gW3t[ky * 4096 + e];
    }
    if (t < 128) {
        float sv, cv;
        sincospif((float)t * (1.0f / 64.0f), &sv, &cv);
        tab4[t] = make_float4(cv, cv, sv, sv);
    }
    __syncthreads();

    int o = t & 63, sg = t >> 6;
    const float2* Wb = (sg < 2) ? Wb0 : Wb1;
    ull acc[8];
    #pragma unroll
    for (int q = 0; q < 8; q++) acc[q] = 0ull;
    for (int j = 0; j < 64; j++) {
        float2 wv = Wb[j * 64 + o];
        ull wr2 = pack2(wv.x, wv.x), wi2 = pack2(wv.y, wv.y);
        #pragma unroll
        for (int q = 0; q < 8; q++) {
            ulonglong2 tp = *(const ulonglong2*)&Ts4[(sg * 8 + q) * 64 + j];
            ffma2(acc[q], wr2, tp.x);
            ffma2(acc[q], wi2, tp.y);
        }
    }
    __syncthreads();
    #pragma unroll
    for (int q = 0; q < 8; q++) {
        int s_ = sg * 8 + q;
        float re, im;
        unpack2(acc[q], re, im);
        Fs[s_ * 64 + o] = make_float2(re, im);
    }
    __syncthreads();

    for (int e = t; e < 1024; e += 256) {
        int k = e >> 6, oo = e & 63;
        if (k == 0) {
            float2 f = Fs[16 * 64 + oo];
            PQ[oo] = make_float4(f.x, f.y, f.y, -f.x);
        } else {
            float2 fa = Fs[k * 64 + oo], fb = Fs[(32 - k) * 64 + oo];
            PQ[k * 64 + oo] = make_float4(fa.x + fb.x, fa.y + fb.y, -(fa.y - fb.y), fa.x - fb.x);
        }
    }
    __syncthreads();

    int ug = t >> 6;
    float2 F0 = Fs[o];
    float4 pq[16];
    #pragma unroll
    for (int k = 0; k < 16; k++) pq[k] = PQ[k * 64 + o];

    for (int q = 0; q < 32; q++) {
        int u = ug * 32 + q;
        ull acc2 = pack2(F0.x, F0.y);
        int idx = u;
        #pragma unroll
        for (int k = 1; k < 16; k++) {
            const ull* cs = (const ull*)&tab4[idx];
            ffma2(acc2, cs[0], ((const ull*)&pq[k])[0]);
            ffma2(acc2, cs[1], ((const ull*)&pq[k])[1]);
            idx = (idx + u) & 127;
        }
        {
            const ull* cs = (const ull*)&tab4[(16 * u) & 127];
            ffma2(acc2, cs[0], ((const ull*)&pq[0])[0]);
            ffma2(acc2, cs[1], ((const ull*)&pq[0])[1]);
        }
        float re, im;
        unpack2(acc2, re, im);
        gD[(((size_t)b * 128 + u) * 16 + ky) * 64 + o] = make_float2(re, im);
    }
}

// ---------------- K5: inverse ky + both MLPs ----------------
#define OFF_XHI   0u
#define OFF_XLO   18432u
#define OFF_HHI   36864u
#define OFF_HLO   71680u
#define SMEM_K5   106496

__global__ __launch_bounds__(256, 2) void k5_mma(
    const float* __restrict__ bb1, const float* __restrict__ bb2,
    const float* __restrict__ fb1, const float* __restrict__ fb2,
    float* __restrict__ out) {
    extern __shared__ __align__(16) char sm[];
    unsigned sb = smem_u32(sm);
    int t = threadIdx.x, w = t >> 5, l = t & 31;
    int blk = blockIdx.x;

    float2* E2 = (float2*)(sm + OFF_HHI);
    float* Dp = (float*)(sm + OFF_HHI + 32768);
    for (int e = t; e < 2048; e += 256)
        ((float4*)E2)[e] = ((const float4*)gE2)[e];
    for (int e = t; e < 1024; e += 256) {
        int ky = e >> 6, o = e & 63;
        float2 d = gD[(size_t)blk * 1024 + e];
        float sc = (ky ? 2.0f : 1.0f) * (1.0f / 16384.0f);
        Dp[(2 * ky) * 64 + o] = d.x * sc;
        Dp[(2 * ky + 1) * 64 + o] = -d.y * sc;
    }
    __syncthreads();

    {
        int rg = t >> 4, cg = t & 15;
        int r0 = rg * 8, c0 = cg * 4;
        ull acc[8][2];
        #pragma unroll
        for (int j = 0; j < 8; j++) { acc[j][0] = 0ull; acc[j][1] = 0ull; }
        const ull* E2u = (const ull*)E2;
        for (int c = 0; c < 32; c++) {
            ulonglong2 dd = *(const ulonglong2*)&Dp[c * 64 + c0];
            #pragma unroll
            for (int j = 0; j < 8; j++) {
                ull e2 = E2u[(r0 + j) * 32 + c];
                ffma2(acc[j][0], e2, dd.x);
                ffma2(acc[j][1], e2, dd.y);
            }
        }
        #pragma unroll
        for (int j = 0; j < 8; j++) {
            float x0, x1, x2, x3;
            unpack2(acc[j][0], x0, x1);
            unpack2(acc[j][1], x2, x3);
            unsigned hA, lA, hB, lB;
            split2(x0, x1, hA, lA);
            split2(x2, x3, hB, lB);
            unsigned relb = (unsigned)(r0 + j) * 144u + (unsigned)c0 * 2u;
            *(uint2*)(sm + OFF_XHI + relb) = make_uint2(hA, hB);
            *(uint2*)(sm + OFF_XLO + relb) = make_uint2(lA, lB);
        }
    }

    size_t rowBase = (size_t)blk * 128;
    int wm = w & 1, wn = w >> 1;
    unsigned kA = ((l >> 4) & 1) * 8;
    unsigned rowA = (unsigned)(wm * 64 + (l & 7) + ((l >> 3) & 1) * 8);

    for (int p = 0; p < 2; p++) {
        __syncthreads();
        const float* B1 = p ? fb1 : bb1;
        const float* B2 = p ? fb2 : bb2;

        {
            float acc[4][4][4];
            #pragma unroll
            for (int a = 0; a < 4; a++)
                #pragma unroll
                for (int b = 0; b < 4; b++)
                    #pragma unroll
                    for (int c = 0; c < 4; c++) acc[a][b][c] = 0.f;

            unsigned aXhi = sb + OFF_XHI + rowA * 144 + kA * 2;
            unsigned aXlo = sb + OFF_XLO + rowA * 144 + kA * 2;
            const uint4* F1 = (const uint4*)gF1 + ((p * 4 + wn) * 4) * 4 * 32 + l;

            #pragma unroll
            for (int ki = 0; ki < 4; ki++) {
                unsigned kb = ki * 32;
                unsigned ah[4][4], al[4][4];
                uint4 bh[2], bl[2];
                #pragma unroll
                for (int mf = 0; mf < 4; mf++) {
                    ldm4(ah[mf], aXhi + mf * (16 * 144) + kb);
                    ldm4(al[mf], aXlo + mf * (16 * 144) + kb);
                }
                bh[0] = F1[(ki * 4 + 0) * 32];
                bh[1] = F1[(ki * 4 + 1) * 32];
                bl[0] = F1[(ki * 4 + 2) * 32];
                bl[1] = F1[(ki * 4 + 3) * 32];
                const unsigned* bhp = (const unsigned*)bh;
                const unsigned* blp = (const unsigned*)bl;
                #pragma unroll
                for (int mf = 0; mf < 4; mf++)
                    #pragma unroll
                    for (int nf = 0; nf < 4; nf++)
                        mma16816(acc[mf][nf], ah[mf], &bhp[nf * 2]);
                #pragma unroll
                for (int mf = 0; mf < 4; mf++)
                    #pragma unroll
                    for (int nf = 0; nf < 4; nf++)
                        mma16816(acc[mf][nf], ah[mf], &blp[nf * 2]);
                #pragma unroll
                for (int mf = 0; mf < 4; mf++)
                    #pragma unroll
                    for (int nf = 0; nf < 4; nf++)
                        mma16816(acc[mf][nf], al[mf], &bhp[nf * 2]);
            }
            int rbase = wm * 64 + (l >> 2);
            int ncol = 2 * (l & 3);
            #pragma unroll
            for (int nf = 0; nf < 4; nf++) {
                int n = wn * 32 + nf * 8 + ncol;
                float2 bv = *(const float2*)(B1 + n);
                #pragma unroll
                for (int mf = 0; mf < 4; mf++)
                    #pragma unroll
                    for (int half = 0; half < 2; half++) {
                        int r = rbase + mf * 16 + half * 8;
                        float v0 = fmaxf(acc[mf][nf][half * 2 + 0] + bv.x, 0.f);
                        float v1 = fmaxf(acc[mf][nf][half * 2 + 1] + bv.y, 0.f);
                        unsigned hp, lp;
                        split2(v0, v1, hp, lp);
                        unsigned off = (unsigned)r * 272u + (unsigned)n * 2u;
                        *(unsigned*)(sm + OFF_HHI + off) = hp;
                        *(unsigned*)(sm + OFF_HLO + off) = lp;
                    }
            }
        }
        __syncthreads();

        {
            float acc[4][2][4];
            #pragma unroll
            for (int a = 0; a < 4; a++)
                #pragma unroll
                for (int b = 0; b < 2; b++)
                    #pragma unroll
                    for (int c = 0; c < 4; c++) acc[a][b][c] = 0.f;

            unsigned aHhi = sb + OFF_HHI + rowA * 272 + kA * 2;
            unsigned aHlo = sb + OFF_HLO + rowA * 272 + kA * 2;
            const uint4* F2 = (const uint4*)gF2 + ((p * 4 + wn) * 8) * 2 * 32 + l;

            #pragma unroll
            for (int ki = 0; ki < 8; ki++) {
                unsigned kb = ki * 32;
                unsigned ah[4][4], al[4][4];
                uint4 bh4 = F2[(ki * 2 + 0) * 32];
                uint4 bl4 = F2[(ki * 2 + 1) * 32];
                const unsigned* bh = (const unsigned*)&bh4;
                const unsigned* bl = (const unsigned*)&bl4;
                #pragma unroll
                for (int mf = 0; mf < 4; mf++) {
                    ldm4(ah[mf], aHhi + mf * (16 * 272) + kb);
                    ldm4(al[mf], aHlo + mf * (16 * 272) + kb);
                }
                #pragma unroll
                for (int mf = 0; mf < 4; mf++)
                    #pragma unroll
                    for (int nf = 0; nf < 2; nf++)
                        mma16816(acc[mf][nf], ah[mf], &bh[nf * 2]);
                #pragma unroll
                for (int mf = 0; mf < 4; mf++)
                    #pragma unroll
                    for (int nf = 0; nf < 2; nf++)
                        mma16816(acc[mf][nf], ah[mf], &bl[nf * 2]);
                #pragma unroll
                for (int mf = 0; mf < 4; mf++)
                    #pragma unroll
                    for (int nf = 0; nf < 2; nf++)
                        mma16816(acc[mf][nf], al[mf], &bh[nf * 2]);
            }
            float* outp = out + (size_t)p * 33554432ull + rowBase * 64;
            int rbase = wm * 64 + (l >> 2);
            int ncol = 2 * (l & 3);
            #pragma unroll
            for (int nf = 0; nf < 2; nf++) {
                int n = wn * 16 + nf * 8 + ncol;
                float2 bv = *(const float2*)(B2 + n);
                #pragma unroll
                for (int mf = 0; mf < 4; mf++)
                    #pragma unroll
                    for (int half = 0; half < 2; half++) {
                        int r = rbase + mf * 16 + half * 8;
                        float2 val = make_float2(acc[mf][nf][half * 2 + 0] + bv.x,
                                                 acc[mf][nf][half * 2 + 1] + bv.y);
                        *(float2*)(outp + (size_t)r * 64 + n) = val;
                    }
            }
        }
    }
}

// ---------------------------------------------------------------------------
extern "C" void kernel_launch(void* const* d_in, const int* in_sizes, int n_in,
                              void* d_out, int out_size) {
    const float* x = (const float*)d_in[0];
    const float* w0 = (const float*)d_in[1];
    const float* w1 = (const float*)d_in[2];
    const float* w2 = (const float*)d_in[3];
    const float* w3 = (const float*)d_in[4];
    const float* bw1 = (const float*)d_in[5];
    const float* bb1 = (const float*)d_in[6];
    const float* bw2 = (const float*)d_in[7];
    const float* bb2 = (const float*)d_in[8];
    const float* fw1 = (const float*)d_in[9];
    const float* fb1 = (const float*)d_in[10];
    const float* fw2 = (const float*)d_in[11];
    const float* fb2 = (const float*)d_in[12];
    float* out = (float*)d_out;

    const int SM_PF = 71680;
    const int SM_K3AP = 69632;
    const int SM_K1 = 40960;
    const int SM_K2 = 49152;
    const int SM_K3B4 = 100352;
    cudaFuncSetAttribute(prep_frag, cudaFuncAttributeMaxDynamicSharedMemorySize, SM_PF);
    cudaFuncSetAttribute(prep_k3a, cudaFuncAttributeMaxDynamicSharedMemorySize, SM_K3AP);
    cudaFuncSetAttribute(k1_stageA, cudaFuncAttributeMaxDynamicSharedMemorySize, SM_K1);
    cudaFuncSetAttribute(k2_stageB, cudaFuncAttributeMaxDynamicSharedMemorySize, SM_K2);
    cudaFuncSetAttribute(k3b4_mix_inv, cudaFuncAttributeMaxDynamicSharedMemorySize, SM_K3B4);
    cudaFuncSetAttribute(k5_mma, cudaFuncAttributeMaxDynamicSharedMemorySize, SMEM_K5);

    prep_frag<<<2, 256, SM_PF>>>(bw1, fw1, bw2, fw2);
    prep_k3a<<<32, 256, SM_K3AP>>>(w0, w2);
    prep_spec<<<256, 256>>>(w0, w1, w2, w3);
    prep_e<<<40, 256>>>();
    k1_stageA<<<NB * 128, 256, SM_K1>>>(x);
    k2_stageB<<<NB * 16, 256, SM_K2>>>();
    k3a_mma<<<NB * 32, 256>>>();
    k3b4_mix_inv<<<NB * 16, 256, SM_K3B4>>>();
    k5_mma<<<NB * 128, 256, SMEM_K5>>>(bb1, bb2, fb1, fb2, out);
}